// round 4
// baseline (speedup 1.0000x reference)
#include <cuda_runtime.h>
#include <cstdint>

#define MAXN 4096

// Per-x-query: wa, wb, wc, bitcast(I)
__device__ float4 g_xw[MAXN];
// Per-y-query: h0, h2, h1, h3*ratio
__device__ float4 g_yw[MAXN];
__device__ int    g_yJ[MAXN];

__device__ __forceinline__ int searchsorted_inner(const float* __restrict__ axis, float q, int n) {
    // searchsorted(axis[1:n-1], q, side='left'): smallest idx in [0, n-2] with axis[1+idx] >= q
    int lo = 0, hi = n - 2;
    while (lo < hi) {
        int mid = (lo + hi) >> 1;
        if (axis[1 + mid] < q) lo = mid + 1; else hi = mid;
    }
    return lo;
}

__global__ void precompute_weights(const float* __restrict__ xaxis,
                                   const float* __restrict__ yaxis,
                                   const float* __restrict__ xs,
                                   const float* __restrict__ ys,
                                   int n) {
    int k = blockIdx.x * blockDim.x + threadIdx.x;
    if (k >= n) return;

    // ---- x direction ----
    {
        float q = xs[k];
        int I = searchsorted_inner(xaxis, q, n);
        float x0 = xaxis[I];
        float x1 = xaxis[I + 1];
        int i2 = (I + 2 < n) ? I + 2 : n - 1;     // defensive clamp (domain keeps I+2 < n)
        float x2 = xaxis[i2];
        float dx = x1 - x0;
        float t  = (q - x0) / dx;
        float t2 = t * t, t3 = t2 * t;
        float h0 = 1.0f - 3.0f * t2 + 2.0f * t3;
        float h1 = t - 2.0f * t2 + t3;
        float h2 = 3.0f * t2 - 2.0f * t3;
        float h3 = t3 - t2;
        float r  = dx / (x2 - x1);
        float4 w;
        w.x = h0 - h1;               // weight on S[I]
        w.y = h1 + h2 - h3 * r;      // weight on S[I+1]
        w.z = h3 * r;                // weight on S[I+2]
        w.w = __int_as_float(I);
        g_xw[k] = w;
    }

    // ---- y direction ----
    {
        float q = ys[k];
        int J = searchsorted_inner(yaxis, q, n);
        float y0 = yaxis[J];
        float y1 = yaxis[J + 1];
        int j2 = (J + 2 < n) ? J + 2 : n - 1;
        float y2 = yaxis[j2];
        float dy = y1 - y0;
        float t  = (q - y0) / dy;
        float t2 = t * t, t3 = t2 * t;
        float h0 = 1.0f - 3.0f * t2 + 2.0f * t3;
        float h1 = t - 2.0f * t2 + t3;
        float h2 = 3.0f * t2 - 2.0f * t3;
        float h3 = t3 - t2;
        float r  = dy / (y2 - y1);
        float4 w;
        w.x = h0;        // weight on out[.., J]
        w.y = h2;        // weight on out[.., J+1]
        w.z = h1;        // weight on (S[J+1,k]-S[J,k])
        w.w = h3 * r;    // weight on (S[J+2,k]-S[J+1,k])
        g_yw[k] = w;
        g_yJ[k] = J;
    }
}

// ───────────────────────── Specialized N=1024 kernel ─────────────────────────
// One CTA (256 threads) per output row (b, my). Thread t owns elements
// 4t..4t+3 in BOTH phases:
//   staging: load float4 group t of rows J/J+1/J+2 (coalesced), write combined
//            rowC[i] = yw.x*S[J,i] + yw.y*S[J+1,i] to smem, keep
//            rowD (coalesced term) in 4 registers.
//   compute: 4 elements, 12 gather LDS from rowC, one STG.128.
__global__ __launch_bounds__(256) void hermite2d_n1024(
    const float* __restrict__ signal,
    float* __restrict__ out) {
    __shared__ float rowC[1024];

    const int t  = threadIdx.x;
    const int bm = blockIdx.x;
    const int b  = bm >> 10;
    const int my = bm & 1023;

    const int    J  = g_yJ[my];
    const float4 yw = g_yw[my];

    const float* base = signal + (((size_t)b << 10) + (size_t)J) * 1024u;
    const float4* __restrict__ srcJ  = reinterpret_cast<const float4*>(base);
    const float4* __restrict__ srcJ1 = reinterpret_cast<const float4*>(base + 1024);
    const float4* __restrict__ srcJ2 = reinterpret_cast<const float4*>(base + 2048);

    float4 a = srcJ[t];
    float4 c = srcJ1[t];
    float4 e = srcJ2[t];

    float4 C;
    C.x = yw.x * a.x + yw.y * c.x;
    C.y = yw.x * a.y + yw.y * c.y;
    C.z = yw.x * a.z + yw.y * c.z;
    C.w = yw.x * a.w + yw.y * c.w;
    reinterpret_cast<float4*>(rowC)[t] = C;

    // coalesced y-slope term stays in registers (this thread consumes exactly these)
    float D0 = yw.z * (c.x - a.x) + yw.w * (e.x - c.x);
    float D1 = yw.z * (c.y - a.y) + yw.w * (e.y - c.y);
    float D2 = yw.z * (c.z - a.z) + yw.w * (e.z - c.z);
    float D3 = yw.z * (c.w - a.w) + yw.w * (e.w - c.w);

    __syncthreads();

    const int k0 = t << 2;
    const float4 w0 = g_xw[k0 + 0];
    const float4 w1 = g_xw[k0 + 1];
    const float4 w2 = g_xw[k0 + 2];
    const float4 w3 = g_xw[k0 + 3];
    const int I0 = __float_as_int(w0.w);
    const int I1 = __float_as_int(w1.w);
    const int I2 = __float_as_int(w2.w);
    const int I3 = __float_as_int(w3.w);

    float4 r;
    r.x = w0.x * rowC[I0] + w0.y * rowC[I0 + 1] + w0.z * rowC[I0 + 2] + D0;
    r.y = w1.x * rowC[I1] + w1.y * rowC[I1 + 1] + w1.z * rowC[I1 + 2] + D1;
    r.z = w2.x * rowC[I2] + w2.y * rowC[I2 + 1] + w2.z * rowC[I2 + 2] + D2;
    r.w = w3.x * rowC[I3] + w3.y * rowC[I3 + 1] + w3.z * rowC[I3 + 2] + D3;

    float4* orow = reinterpret_cast<float4*>(out + (((size_t)b << 10) + (size_t)my) * 1024u);
    orow[t] = r;
}

// ───────────────────────── Generic fallback (any n % 4 == 0) ─────────────────
__global__ __launch_bounds__(256) void hermite2d_generic(
    const float* __restrict__ signal,
    float* __restrict__ out,
    int n) {
    extern __shared__ float sm[];          // 2*n floats
    float* rowC = sm;
    float* rowD = sm + n;

    int bm = blockIdx.x;
    int b  = bm / n;
    int my = bm - b * n;

    int    J  = g_yJ[my];
    float4 yw = g_yw[my];

    const float* base = signal + ((size_t)b * n + J) * (size_t)n;
    int nv = n >> 2;
    const float4* srcJ  = reinterpret_cast<const float4*>(base);
    const float4* srcJ1 = reinterpret_cast<const float4*>(base + n);
    const float4* srcJ2 = reinterpret_cast<const float4*>(base + 2 * (size_t)n);
    float4* dstC = reinterpret_cast<float4*>(rowC);
    float4* dstD = reinterpret_cast<float4*>(rowD);
    for (int i = threadIdx.x; i < nv; i += blockDim.x) {
        float4 a = srcJ[i];
        float4 c = srcJ1[i];
        float4 e = srcJ2[i];
        float4 C, D;
        C.x = yw.x * a.x + yw.y * c.x;
        C.y = yw.x * a.y + yw.y * c.y;
        C.z = yw.x * a.z + yw.y * c.z;
        C.w = yw.x * a.w + yw.y * c.w;
        D.x = yw.z * (c.x - a.x) + yw.w * (e.x - c.x);
        D.y = yw.z * (c.y - a.y) + yw.w * (e.y - c.y);
        D.z = yw.z * (c.z - a.z) + yw.w * (e.z - c.z);
        D.w = yw.z * (c.w - a.w) + yw.w * (e.w - c.w);
        dstC[i] = C;
        dstD[i] = D;
    }
    __syncthreads();

    float* orow = out + ((size_t)b * n + my) * (size_t)n;
    for (int k = threadIdx.x; k < n; k += blockDim.x) {
        float4 xw = g_xw[k];
        int I = __float_as_int(xw.w);
        orow[k] = xw.x * rowC[I] + xw.y * rowC[I + 1] + xw.z * rowC[I + 2] + rowD[k];
    }
}

extern "C" void kernel_launch(void* const* d_in, const int* in_sizes, int n_in,
                              void* d_out, int out_size) {
    const float* xaxis  = (const float*)d_in[0];
    const float* yaxis  = (const float*)d_in[1];
    const float* signal = (const float*)d_in[2];
    const float* xs     = (const float*)d_in[3];
    const float* ys     = (const float*)d_in[4];
    float* out = (float*)d_out;

    int n = in_sizes[0];                 // N (square grid, Mx = My = N)
    int B = in_sizes[2] / (n * n);       // batch

    precompute_weights<<<(n + 255) / 256, 256>>>(xaxis, yaxis, xs, ys, n);

    if (n == 1024) {
        hermite2d_n1024<<<B * n, 256>>>(signal, out);
    } else {
        size_t smem = 2 * (size_t)n * sizeof(float);
        hermite2d_generic<<<B * n, 256, smem>>>(signal, out, n);
    }
}

// round 5
// speedup vs baseline: 1.3504x; 1.3504x over previous
#include <cuda_runtime.h>
#include <cstdint>

#define MAXN 4096

// Per-x-query: wa, wb, wc, bitcast(I)
__device__ float4 g_xw[MAXN];
// Per-y-query: h0, h2, h1, h3*ratio
__device__ float4 g_yw[MAXN];
__device__ int    g_yJ[MAXN];

__device__ __forceinline__ int searchsorted_inner(const float* __restrict__ axis, float q, int n) {
    // searchsorted(axis[1:n-1], q, side='left'): smallest idx in [0, n-2] with axis[1+idx] >= q
    int lo = 0, hi = n - 2;
    while (lo < hi) {
        int mid = (lo + hi) >> 1;
        if (axis[1 + mid] < q) lo = mid + 1; else hi = mid;
    }
    return lo;
}

__global__ void precompute_weights(const float* __restrict__ xaxis,
                                   const float* __restrict__ yaxis,
                                   const float* __restrict__ xs,
                                   const float* __restrict__ ys,
                                   int n) {
    int k = blockIdx.x * blockDim.x + threadIdx.x;
    if (k >= n) return;

    // ---- x direction ----
    {
        float q = xs[k];
        int I = searchsorted_inner(xaxis, q, n);
        float x0 = xaxis[I];
        float x1 = xaxis[I + 1];
        int i2 = (I + 2 < n) ? I + 2 : n - 1;     // defensive clamp (domain keeps I+2 < n)
        float x2 = xaxis[i2];
        float dx = x1 - x0;
        float t  = (q - x0) / dx;
        float t2 = t * t, t3 = t2 * t;
        float h0 = 1.0f - 3.0f * t2 + 2.0f * t3;
        float h1 = t - 2.0f * t2 + t3;
        float h2 = 3.0f * t2 - 2.0f * t3;
        float h3 = t3 - t2;
        float r  = dx / (x2 - x1);
        float4 w;
        w.x = h0 - h1;               // weight on S[I]
        w.y = h1 + h2 - h3 * r;      // weight on S[I+1]
        w.z = h3 * r;                // weight on S[I+2]
        w.w = __int_as_float(I);
        g_xw[k] = w;
    }

    // ---- y direction ----
    {
        float q = ys[k];
        int J = searchsorted_inner(yaxis, q, n);
        float y0 = yaxis[J];
        float y1 = yaxis[J + 1];
        int j2 = (J + 2 < n) ? J + 2 : n - 1;
        float y2 = yaxis[j2];
        float dy = y1 - y0;
        float t  = (q - y0) / dy;
        float t2 = t * t, t3 = t2 * t;
        float h0 = 1.0f - 3.0f * t2 + 2.0f * t3;
        float h1 = t - 2.0f * t2 + t3;
        float h2 = 3.0f * t2 - 2.0f * t3;
        float h3 = t3 - t2;
        float r  = dy / (y2 - y1);
        float4 w;
        w.x = h0;        // weight on out[.., J]
        w.y = h2;        // weight on out[.., J+1]
        w.z = h1;        // weight on (S[J+1,k]-S[J,k])
        w.w = h3 * r;    // weight on (S[J+2,k]-S[J+1,k])
        g_yw[k] = w;
        g_yJ[k] = J;
    }
}

// ───────────────────────── Specialized N=1024 kernel ─────────────────────────
// One CTA (256 threads) per output row (b, my). Thread t owns elements
// {t, t+256, t+512, t+768} in BOTH phases, so EVERY global/table/smem access
// except the inherent rowC gather is warp-coalesced:
//   staging: 12 scalar coalesced LDG (rows J/J+1/J+2), 4 coalesced STS (rowC),
//            rowD term kept in 4 registers.
//   compute: 4 coalesced g_xw LDG.128 (512B/warp contiguous), 12 gather LDS,
//            4 coalesced scalar STG.
__global__ __launch_bounds__(256) void hermite2d_n1024(
    const float* __restrict__ signal,
    float* __restrict__ out) {
    __shared__ float rowC[1024];

    const int t  = threadIdx.x;
    const int bm = blockIdx.x;
    const int b  = bm >> 10;
    const int my = bm & 1023;

    const int    J  = g_yJ[my];
    const float4 yw = g_yw[my];

    const float* __restrict__ base = signal + (((size_t)b << 10) + (size_t)J) * 1024u;

    float a0 = base[t +   0];
    float a1 = base[t + 256];
    float a2 = base[t + 512];
    float a3 = base[t + 768];
    float c0 = base[1024 + t +   0];
    float c1 = base[1024 + t + 256];
    float c2 = base[1024 + t + 512];
    float c3 = base[1024 + t + 768];
    float e0 = base[2048 + t +   0];
    float e1 = base[2048 + t + 256];
    float e2 = base[2048 + t + 512];
    float e3 = base[2048 + t + 768];

    rowC[t +   0] = yw.x * a0 + yw.y * c0;
    rowC[t + 256] = yw.x * a1 + yw.y * c1;
    rowC[t + 512] = yw.x * a2 + yw.y * c2;
    rowC[t + 768] = yw.x * a3 + yw.y * c3;

    // coalesced y-slope term stays in registers (this thread consumes exactly these)
    const float D0 = yw.z * (c0 - a0) + yw.w * (e0 - c0);
    const float D1 = yw.z * (c1 - a1) + yw.w * (e1 - c1);
    const float D2 = yw.z * (c2 - a2) + yw.w * (e2 - c2);
    const float D3 = yw.z * (c3 - a3) + yw.w * (e3 - c3);

    __syncthreads();

    const float4 w0 = g_xw[t +   0];
    const float4 w1 = g_xw[t + 256];
    const float4 w2 = g_xw[t + 512];
    const float4 w3 = g_xw[t + 768];
    const int I0 = __float_as_int(w0.w);
    const int I1 = __float_as_int(w1.w);
    const int I2 = __float_as_int(w2.w);
    const int I3 = __float_as_int(w3.w);

    const float r0 = w0.x * rowC[I0] + w0.y * rowC[I0 + 1] + w0.z * rowC[I0 + 2] + D0;
    const float r1 = w1.x * rowC[I1] + w1.y * rowC[I1 + 1] + w1.z * rowC[I1 + 2] + D1;
    const float r2 = w2.x * rowC[I2] + w2.y * rowC[I2 + 1] + w2.z * rowC[I2 + 2] + D2;
    const float r3 = w3.x * rowC[I3] + w3.y * rowC[I3 + 1] + w3.z * rowC[I3 + 2] + D3;

    float* __restrict__ orow = out + (((size_t)b << 10) + (size_t)my) * 1024u;
    orow[t +   0] = r0;
    orow[t + 256] = r1;
    orow[t + 512] = r2;
    orow[t + 768] = r3;
}

// ───────────────────────── Generic fallback (any n % 4 == 0) ─────────────────
__global__ __launch_bounds__(256) void hermite2d_generic(
    const float* __restrict__ signal,
    float* __restrict__ out,
    int n) {
    extern __shared__ float sm[];          // 2*n floats
    float* rowC = sm;
    float* rowD = sm + n;

    int bm = blockIdx.x;
    int b  = bm / n;
    int my = bm - b * n;

    int    J  = g_yJ[my];
    float4 yw = g_yw[my];

    const float* base = signal + ((size_t)b * n + J) * (size_t)n;
    int nv = n >> 2;
    const float4* srcJ  = reinterpret_cast<const float4*>(base);
    const float4* srcJ1 = reinterpret_cast<const float4*>(base + n);
    const float4* srcJ2 = reinterpret_cast<const float4*>(base + 2 * (size_t)n);
    float4* dstC = reinterpret_cast<float4*>(rowC);
    float4* dstD = reinterpret_cast<float4*>(rowD);
    for (int i = threadIdx.x; i < nv; i += blockDim.x) {
        float4 a = srcJ[i];
        float4 c = srcJ1[i];
        float4 e = srcJ2[i];
        float4 C, D;
        C.x = yw.x * a.x + yw.y * c.x;
        C.y = yw.x * a.y + yw.y * c.y;
        C.z = yw.x * a.z + yw.y * c.z;
        C.w = yw.x * a.w + yw.y * c.w;
        D.x = yw.z * (c.x - a.x) + yw.w * (e.x - c.x);
        D.y = yw.z * (c.y - a.y) + yw.w * (e.y - c.y);
        D.z = yw.z * (c.z - a.z) + yw.w * (e.z - c.z);
        D.w = yw.z * (c.w - a.w) + yw.w * (e.w - c.w);
        dstC[i] = C;
        dstD[i] = D;
    }
    __syncthreads();

    float* orow = out + ((size_t)b * n + my) * (size_t)n;
    for (int k = threadIdx.x; k < n; k += blockDim.x) {
        float4 xw = g_xw[k];
        int I = __float_as_int(xw.w);
        orow[k] = xw.x * rowC[I] + xw.y * rowC[I + 1] + xw.z * rowC[I + 2] + rowD[k];
    }
}

extern "C" void kernel_launch(void* const* d_in, const int* in_sizes, int n_in,
                              void* d_out, int out_size) {
    const float* xaxis  = (const float*)d_in[0];
    const float* yaxis  = (const float*)d_in[1];
    const float* signal = (const float*)d_in[2];
    const float* xs     = (const float*)d_in[3];
    const float* ys     = (const float*)d_in[4];
    float* out = (float*)d_out;

    int n = in_sizes[0];                 // N (square grid, Mx = My = N)
    int B = in_sizes[2] / (n * n);       // batch

    precompute_weights<<<(n + 255) / 256, 256>>>(xaxis, yaxis, xs, ys, n);

    if (n == 1024) {
        hermite2d_n1024<<<B * n, 256>>>(signal, out);
    } else {
        size_t smem = 2 * (size_t)n * sizeof(float);
        hermite2d_generic<<<B * n, 256, smem>>>(signal, out, n);
    }
}

// round 6
// speedup vs baseline: 1.4695x; 1.0882x over previous
#include <cuda_runtime.h>
#include <cstdint>

#define MAXN 4096

// Per-x-query: wa, wb, wc, bitcast(I)
__device__ float4 g_xw[MAXN];
// Per-y-query: h0, h2, h1, h3*ratio
__device__ float4 g_yw[MAXN];
__device__ int    g_yJ[MAXN];

__device__ __forceinline__ int searchsorted_inner(const float* __restrict__ axis, float q, int n) {
    // searchsorted(axis[1:n-1], q, side='left'): smallest idx in [0, n-2] with axis[1+idx] >= q
    int lo = 0, hi = n - 2;
    while (lo < hi) {
        int mid = (lo + hi) >> 1;
        if (axis[1 + mid] < q) lo = mid + 1; else hi = mid;
    }
    return lo;
}

__global__ void precompute_weights(const float* __restrict__ xaxis,
                                   const float* __restrict__ yaxis,
                                   const float* __restrict__ xs,
                                   const float* __restrict__ ys,
                                   int n) {
    int k = blockIdx.x * blockDim.x + threadIdx.x;
    if (k >= n) return;

    // ---- x direction ----
    {
        float q = xs[k];
        int I = searchsorted_inner(xaxis, q, n);
        float x0 = xaxis[I];
        float x1 = xaxis[I + 1];
        int i2 = (I + 2 < n) ? I + 2 : n - 1;     // defensive clamp (domain keeps I+2 < n)
        float x2 = xaxis[i2];
        float dx = x1 - x0;
        float t  = (q - x0) / dx;
        float t2 = t * t, t3 = t2 * t;
        float h0 = 1.0f - 3.0f * t2 + 2.0f * t3;
        float h1 = t - 2.0f * t2 + t3;
        float h2 = 3.0f * t2 - 2.0f * t3;
        float h3 = t3 - t2;
        float r  = dx / (x2 - x1);
        float4 w;
        w.x = h0 - h1;               // weight on S[I]
        w.y = h1 + h2 - h3 * r;      // weight on S[I+1]
        w.z = h3 * r;                // weight on S[I+2]
        w.w = __int_as_float(I);
        g_xw[k] = w;
    }

    // ---- y direction ----
    {
        float q = ys[k];
        int J = searchsorted_inner(yaxis, q, n);
        float y0 = yaxis[J];
        float y1 = yaxis[J + 1];
        int j2 = (J + 2 < n) ? J + 2 : n - 1;
        float y2 = yaxis[j2];
        float dy = y1 - y0;
        float t  = (q - y0) / dy;
        float t2 = t * t, t3 = t2 * t;
        float h0 = 1.0f - 3.0f * t2 + 2.0f * t3;
        float h1 = t - 2.0f * t2 + t3;
        float h2 = 3.0f * t2 - 2.0f * t3;
        float h3 = t3 - t2;
        float r  = dy / (y2 - y1);
        float4 w;
        w.x = h0;        // weight on out[.., J]
        w.y = h2;        // weight on out[.., J+1]
        w.z = h1;        // weight on (S[J+1,k]-S[J,k])
        w.w = h3 * r;    // weight on (S[J+2,k]-S[J+1,k])
        g_yw[k] = w;
        g_yJ[k] = J;
    }
}

// ─────────────── Specialized N=1024, 4-batches-per-CTA kernel ───────────────
// One CTA (256 threads) handles output row `my` for 4 consecutive batches.
// All 4 batches share J, yw, and — critically — each g_xw float4 load is
// amortized over 4 output elements. Thread t owns elements {t,t+256,t+512,
// t+768}; every access except the inherent rowC gathers is warp-coalesced.
__global__ __launch_bounds__(256) void hermite2d_n1024_b4(
    const float* __restrict__ signal,
    float* __restrict__ out) {
    __shared__ float rowC[4][1024];        // 16 KB

    const int t  = threadIdx.x;
    const int bm = blockIdx.x;
    const int bq = bm >> 10;               // batch quad
    const int my = bm & 1023;

    const int    J  = g_yJ[my];
    const float4 yw = g_yw[my];

    float D[4][4];                         // coalesced y-slope term, register-resident

    #pragma unroll
    for (int bb = 0; bb < 4; bb++) {
        const float* __restrict__ base =
            signal + (((size_t)(4 * bq + bb) << 10) + (size_t)J) * 1024u;
        #pragma unroll
        for (int j = 0; j < 4; j++) {
            const int k = t + 256 * j;
            float a = base[k];
            float c = base[1024 + k];
            float e = base[2048 + k];
            rowC[bb][k] = yw.x * a + yw.y * c;
            D[bb][j]    = yw.z * (c - a) + yw.w * (e - c);
        }
    }
    __syncthreads();

    #pragma unroll
    for (int j = 0; j < 4; j++) {
        const int k = t + 256 * j;
        const float4 w = g_xw[k];
        const int I = __float_as_int(w.w);
        #pragma unroll
        for (int bb = 0; bb < 4; bb++) {
            float val = w.x * rowC[bb][I] + w.y * rowC[bb][I + 1]
                      + w.z * rowC[bb][I + 2] + D[bb][j];
            out[(((size_t)(4 * bq + bb) << 10) + (size_t)my) * 1024u + k] = val;
        }
    }
}

// ─────────────── Specialized N=1024, 1 row per CTA (B % 4 != 0) ─────────────
__global__ __launch_bounds__(256) void hermite2d_n1024(
    const float* __restrict__ signal,
    float* __restrict__ out) {
    __shared__ float rowC[1024];

    const int t  = threadIdx.x;
    const int bm = blockIdx.x;
    const int b  = bm >> 10;
    const int my = bm & 1023;

    const int    J  = g_yJ[my];
    const float4 yw = g_yw[my];

    const float* __restrict__ base = signal + (((size_t)b << 10) + (size_t)J) * 1024u;

    float D[4];
    #pragma unroll
    for (int j = 0; j < 4; j++) {
        const int k = t + 256 * j;
        float a = base[k];
        float c = base[1024 + k];
        float e = base[2048 + k];
        rowC[k] = yw.x * a + yw.y * c;
        D[j]    = yw.z * (c - a) + yw.w * (e - c);
    }
    __syncthreads();

    float* __restrict__ orow = out + (((size_t)b << 10) + (size_t)my) * 1024u;
    #pragma unroll
    for (int j = 0; j < 4; j++) {
        const int k = t + 256 * j;
        const float4 w = g_xw[k];
        const int I = __float_as_int(w.w);
        orow[k] = w.x * rowC[I] + w.y * rowC[I + 1] + w.z * rowC[I + 2] + D[j];
    }
}

// ───────────────────────── Generic fallback (any n % 4 == 0) ─────────────────
__global__ __launch_bounds__(256) void hermite2d_generic(
    const float* __restrict__ signal,
    float* __restrict__ out,
    int n) {
    extern __shared__ float sm[];          // 2*n floats
    float* rowC = sm;
    float* rowD = sm + n;

    int bm = blockIdx.x;
    int b  = bm / n;
    int my = bm - b * n;

    int    J  = g_yJ[my];
    float4 yw = g_yw[my];

    const float* base = signal + ((size_t)b * n + J) * (size_t)n;
    int nv = n >> 2;
    const float4* srcJ  = reinterpret_cast<const float4*>(base);
    const float4* srcJ1 = reinterpret_cast<const float4*>(base + n);
    const float4* srcJ2 = reinterpret_cast<const float4*>(base + 2 * (size_t)n);
    float4* dstC = reinterpret_cast<float4*>(rowC);
    float4* dstD = reinterpret_cast<float4*>(rowD);
    for (int i = threadIdx.x; i < nv; i += blockDim.x) {
        float4 a = srcJ[i];
        float4 c = srcJ1[i];
        float4 e = srcJ2[i];
        float4 C, Dv;
        C.x = yw.x * a.x + yw.y * c.x;
        C.y = yw.x * a.y + yw.y * c.y;
        C.z = yw.x * a.z + yw.y * c.z;
        C.w = yw.x * a.w + yw.y * c.w;
        Dv.x = yw.z * (c.x - a.x) + yw.w * (e.x - c.x);
        Dv.y = yw.z * (c.y - a.y) + yw.w * (e.y - c.y);
        Dv.z = yw.z * (c.z - a.z) + yw.w * (e.z - c.z);
        Dv.w = yw.z * (c.w - a.w) + yw.w * (e.w - c.w);
        dstC[i] = C;
        dstD[i] = Dv;
    }
    __syncthreads();

    float* orow = out + ((size_t)b * n + my) * (size_t)n;
    for (int k = threadIdx.x; k < n; k += blockDim.x) {
        float4 xw = g_xw[k];
        int I = __float_as_int(xw.w);
        orow[k] = xw.x * rowC[I] + xw.y * rowC[I + 1] + xw.z * rowC[I + 2] + rowD[k];
    }
}

extern "C" void kernel_launch(void* const* d_in, const int* in_sizes, int n_in,
                              void* d_out, int out_size) {
    const float* xaxis  = (const float*)d_in[0];
    const float* yaxis  = (const float*)d_in[1];
    const float* signal = (const float*)d_in[2];
    const float* xs     = (const float*)d_in[3];
    const float* ys     = (const float*)d_in[4];
    float* out = (float*)d_out;

    int n = in_sizes[0];                 // N (square grid, Mx = My = N)
    int B = in_sizes[2] / (n * n);       // batch

    precompute_weights<<<(n + 255) / 256, 256>>>(xaxis, yaxis, xs, ys, n);

    if (n == 1024 && (B % 4) == 0) {
        hermite2d_n1024_b4<<<(B / 4) * n, 256>>>(signal, out);
    } else if (n == 1024) {
        hermite2d_n1024<<<B * n, 256>>>(signal, out);
    } else {
        size_t smem = 2 * (size_t)n * sizeof(float);
        hermite2d_generic<<<B * n, 256, smem>>>(signal, out, n);
    }
}

// round 7
// speedup vs baseline: 1.6117x; 1.0968x over previous
#include <cuda_runtime.h>
#include <cstdint>

#define MAXN 4096

// Per-x-query: wa, wb, wc, bitcast(I)
__device__ float4 g_xw[MAXN];
// Per-y-query: h0, h2, h1, h3*ratio
__device__ float4 g_yw[MAXN];
__device__ int    g_yJ[MAXN];

__device__ __forceinline__ int searchsorted_inner(const float* __restrict__ axis, float q, int n) {
    // searchsorted(axis[1:n-1], q, side='left'): smallest idx in [0, n-2] with axis[1+idx] >= q
    int lo = 0, hi = n - 2;
    while (lo < hi) {
        int mid = (lo + hi) >> 1;
        if (axis[1 + mid] < q) lo = mid + 1; else hi = mid;
    }
    return lo;
}

__global__ void precompute_weights(const float* __restrict__ xaxis,
                                   const float* __restrict__ yaxis,
                                   const float* __restrict__ xs,
                                   const float* __restrict__ ys,
                                   int n) {
    int k = blockIdx.x * blockDim.x + threadIdx.x;
    if (k >= n) return;

    // ---- x direction ----
    {
        float q = xs[k];
        int I = searchsorted_inner(xaxis, q, n);
        float x0 = xaxis[I];
        float x1 = xaxis[I + 1];
        int i2 = (I + 2 < n) ? I + 2 : n - 1;     // defensive clamp (domain keeps I+2 < n)
        float x2 = xaxis[i2];
        float dx = x1 - x0;
        float t  = (q - x0) / dx;
        float t2 = t * t, t3 = t2 * t;
        float h0 = 1.0f - 3.0f * t2 + 2.0f * t3;
        float h1 = t - 2.0f * t2 + t3;
        float h2 = 3.0f * t2 - 2.0f * t3;
        float h3 = t3 - t2;
        float r  = dx / (x2 - x1);
        float4 w;
        w.x = h0 - h1;               // weight on S[I]
        w.y = h1 + h2 - h3 * r;      // weight on S[I+1]
        w.z = h3 * r;                // weight on S[I+2]
        w.w = __int_as_float(I);
        g_xw[k] = w;
    }

    // ---- y direction ----
    {
        float q = ys[k];
        int J = searchsorted_inner(yaxis, q, n);
        float y0 = yaxis[J];
        float y1 = yaxis[J + 1];
        int j2 = (J + 2 < n) ? J + 2 : n - 1;
        float y2 = yaxis[j2];
        float dy = y1 - y0;
        float t  = (q - y0) / dy;
        float t2 = t * t, t3 = t2 * t;
        float h0 = 1.0f - 3.0f * t2 + 2.0f * t3;
        float h1 = t - 2.0f * t2 + t3;
        float h2 = 3.0f * t2 - 2.0f * t3;
        float h3 = t3 - t2;
        float r  = dy / (y2 - y1);
        float4 w;
        w.x = h0;        // weight on out[.., J]
        w.y = h2;        // weight on out[.., J+1]
        w.z = h1;        // weight on (S[J+1,k]-S[J,k])
        w.w = h3 * r;    // weight on (S[J+2,k]-S[J+1,k])
        g_yw[k] = w;
        g_yJ[k] = J;
    }
}

// ─────────────── Specialized N=1024, 4-batches-per-CTA, batch-interleaved ───
// One CTA (256 threads) handles output row `my` for 4 consecutive batches.
// Smem is batch-interleaved: rowC4[i] = (C_b0[i], C_b1[i], C_b2[i], C_b3[i]),
// so a single LDS.128 at tap i serves all 4 batches — 3 vector gathers per
// output column instead of 12 scalar gathers. Staging packs all 4 batches at
// the same k and writes one conflict-free STS.128.
__global__ __launch_bounds__(256) void hermite2d_n1024_b4(
    const float* __restrict__ signal,
    float* __restrict__ out) {
    __shared__ float4 rowC4[1024];         // 16 KB, batch-interleaved

    const int t  = threadIdx.x;
    const int bm = blockIdx.x;
    const int bq = bm >> 10;               // batch quad
    const int my = bm & 1023;

    const int    J  = g_yJ[my];
    const float4 yw = g_yw[my];

    const float* __restrict__ base0 = signal + (((size_t)(4 * bq + 0) << 10) + (size_t)J) * 1024u;
    const float* __restrict__ base1 = base0 + (1u << 20);
    const float* __restrict__ base2 = base0 + (2u << 20);
    const float* __restrict__ base3 = base0 + (3u << 20);

    float D[4][4];                         // [bb][j] coalesced y-slope term

    #pragma unroll
    for (int j = 0; j < 4; j++) {
        const int k = t + 256 * j;
        float4 C;
        {
            float a = base0[k], c = base0[1024 + k], e = base0[2048 + k];
            C.x = yw.x * a + yw.y * c;
            D[0][j] = yw.z * (c - a) + yw.w * (e - c);
        }
        {
            float a = base1[k], c = base1[1024 + k], e = base1[2048 + k];
            C.y = yw.x * a + yw.y * c;
            D[1][j] = yw.z * (c - a) + yw.w * (e - c);
        }
        {
            float a = base2[k], c = base2[1024 + k], e = base2[2048 + k];
            C.z = yw.x * a + yw.y * c;
            D[2][j] = yw.z * (c - a) + yw.w * (e - c);
        }
        {
            float a = base3[k], c = base3[1024 + k], e = base3[2048 + k];
            C.w = yw.x * a + yw.y * c;
            D[3][j] = yw.z * (c - a) + yw.w * (e - c);
        }
        rowC4[k] = C;                      // STS.128, conflict-free
    }
    __syncthreads();

    float* __restrict__ o0 = out + (((size_t)(4 * bq + 0) << 10) + (size_t)my) * 1024u;
    float* __restrict__ o1 = o0 + (1u << 20);
    float* __restrict__ o2 = o0 + (2u << 20);
    float* __restrict__ o3 = o0 + (3u << 20);

    #pragma unroll
    for (int j = 0; j < 4; j++) {
        const int k = t + 256 * j;
        const float4 w = g_xw[k];
        const int I = __float_as_int(w.w);

        const float4 p0 = rowC4[I];        // tap I,   all 4 batches (LDS.128)
        const float4 p1 = rowC4[I + 1];    // tap I+1
        const float4 p2 = rowC4[I + 2];    // tap I+2

        o0[k] = w.x * p0.x + w.y * p1.x + w.z * p2.x + D[0][j];
        o1[k] = w.x * p0.y + w.y * p1.y + w.z * p2.y + D[1][j];
        o2[k] = w.x * p0.z + w.y * p1.z + w.z * p2.z + D[2][j];
        o3[k] = w.x * p0.w + w.y * p1.w + w.z * p2.w + D[3][j];
    }
}

// ─────────────── Specialized N=1024, 1 row per CTA (B % 4 != 0) ─────────────
__global__ __launch_bounds__(256) void hermite2d_n1024(
    const float* __restrict__ signal,
    float* __restrict__ out) {
    __shared__ float rowC[1024];

    const int t  = threadIdx.x;
    const int bm = blockIdx.x;
    const int b  = bm >> 10;
    const int my = bm & 1023;

    const int    J  = g_yJ[my];
    const float4 yw = g_yw[my];

    const float* __restrict__ base = signal + (((size_t)b << 10) + (size_t)J) * 1024u;

    float D[4];
    #pragma unroll
    for (int j = 0; j < 4; j++) {
        const int k = t + 256 * j;
        float a = base[k];
        float c = base[1024 + k];
        float e = base[2048 + k];
        rowC[k] = yw.x * a + yw.y * c;
        D[j]    = yw.z * (c - a) + yw.w * (e - c);
    }
    __syncthreads();

    float* __restrict__ orow = out + (((size_t)b << 10) + (size_t)my) * 1024u;
    #pragma unroll
    for (int j = 0; j < 4; j++) {
        const int k = t + 256 * j;
        const float4 w = g_xw[k];
        const int I = __float_as_int(w.w);
        orow[k] = w.x * rowC[I] + w.y * rowC[I + 1] + w.z * rowC[I + 2] + D[j];
    }
}

// ───────────────────────── Generic fallback (any n % 4 == 0) ─────────────────
__global__ __launch_bounds__(256) void hermite2d_generic(
    const float* __restrict__ signal,
    float* __restrict__ out,
    int n) {
    extern __shared__ float sm[];          // 2*n floats
    float* rowC = sm;
    float* rowD = sm + n;

    int bm = blockIdx.x;
    int b  = bm / n;
    int my = bm - b * n;

    int    J  = g_yJ[my];
    float4 yw = g_yw[my];

    const float* base = signal + ((size_t)b * n + J) * (size_t)n;
    int nv = n >> 2;
    const float4* srcJ  = reinterpret_cast<const float4*>(base);
    const float4* srcJ1 = reinterpret_cast<const float4*>(base + n);
    const float4* srcJ2 = reinterpret_cast<const float4*>(base + 2 * (size_t)n);
    float4* dstC = reinterpret_cast<float4*>(rowC);
    float4* dstD = reinterpret_cast<float4*>(rowD);
    for (int i = threadIdx.x; i < nv; i += blockDim.x) {
        float4 a = srcJ[i];
        float4 c = srcJ1[i];
        float4 e = srcJ2[i];
        float4 C, Dv;
        C.x = yw.x * a.x + yw.y * c.x;
        C.y = yw.x * a.y + yw.y * c.y;
        C.z = yw.x * a.z + yw.y * c.z;
        C.w = yw.x * a.w + yw.y * c.w;
        Dv.x = yw.z * (c.x - a.x) + yw.w * (e.x - c.x);
        Dv.y = yw.z * (c.y - a.y) + yw.w * (e.y - c.y);
        Dv.z = yw.z * (c.z - a.z) + yw.w * (e.z - c.z);
        Dv.w = yw.z * (c.w - a.w) + yw.w * (e.w - c.w);
        dstC[i] = C;
        dstD[i] = Dv;
    }
    __syncthreads();

    float* orow = out + ((size_t)b * n + my) * (size_t)n;
    for (int k = threadIdx.x; k < n; k += blockDim.x) {
        float4 xw = g_xw[k];
        int I = __float_as_int(xw.w);
        orow[k] = xw.x * rowC[I] + xw.y * rowC[I + 1] + xw.z * rowC[I + 2] + rowD[k];
    }
}

extern "C" void kernel_launch(void* const* d_in, const int* in_sizes, int n_in,
                              void* d_out, int out_size) {
    const float* xaxis  = (const float*)d_in[0];
    const float* yaxis  = (const float*)d_in[1];
    const float* signal = (const float*)d_in[2];
    const float* xs     = (const float*)d_in[3];
    const float* ys     = (const float*)d_in[4];
    float* out = (float*)d_out;

    int n = in_sizes[0];                 // N (square grid, Mx = My = N)
    int B = in_sizes[2] / (n * n);       // batch

    precompute_weights<<<(n + 255) / 256, 256>>>(xaxis, yaxis, xs, ys, n);

    if (n == 1024 && (B % 4) == 0) {
        hermite2d_n1024_b4<<<(B / 4) * n, 256>>>(signal, out);
    } else if (n == 1024) {
        hermite2d_n1024<<<B * n, 256>>>(signal, out);
    } else {
        size_t smem = 2 * (size_t)n * sizeof(float);
        hermite2d_generic<<<B * n, 256, smem>>>(signal, out, n);
    }
}

// round 8
// speedup vs baseline: 1.6445x; 1.0203x over previous
#include <cuda_runtime.h>
#include <cstdint>

#define MAXN 4096

// Per-x-query: wa, wb, wc, bitcast(I)
__device__ float4 g_xw[MAXN];
// Per-y-query: h0, h2, h1, h3*ratio
__device__ float4 g_yw[MAXN];
__device__ int    g_yJ[MAXN];

__device__ __forceinline__ int searchsorted_inner(const float* __restrict__ axis, float q, int n) {
    // searchsorted(axis[1:n-1], q, side='left'): smallest idx in [0, n-2] with axis[1+idx] >= q
    int lo = 0, hi = n - 2;
    while (lo < hi) {
        int mid = (lo + hi) >> 1;
        if (axis[1 + mid] < q) lo = mid + 1; else hi = mid;
    }
    return lo;
}

__global__ void precompute_weights(const float* __restrict__ xaxis,
                                   const float* __restrict__ yaxis,
                                   const float* __restrict__ xs,
                                   const float* __restrict__ ys,
                                   int n) {
    int k = blockIdx.x * blockDim.x + threadIdx.x;
    if (k >= n) return;

    // ---- x direction ----
    {
        float q = xs[k];
        int I = searchsorted_inner(xaxis, q, n);
        float x0 = xaxis[I];
        float x1 = xaxis[I + 1];
        int i2 = (I + 2 < n) ? I + 2 : n - 1;     // defensive clamp (domain keeps I+2 < n)
        float x2 = xaxis[i2];
        float dx = x1 - x0;
        float t  = (q - x0) / dx;
        float t2 = t * t, t3 = t2 * t;
        float h0 = 1.0f - 3.0f * t2 + 2.0f * t3;
        float h1 = t - 2.0f * t2 + t3;
        float h2 = 3.0f * t2 - 2.0f * t3;
        float h3 = t3 - t2;
        float r  = dx / (x2 - x1);
        float4 w;
        w.x = h0 - h1;               // weight on S[I]
        w.y = h1 + h2 - h3 * r;      // weight on S[I+1]
        w.z = h3 * r;                // weight on S[I+2]
        w.w = __int_as_float(I);
        g_xw[k] = w;
    }

    // ---- y direction ----
    {
        float q = ys[k];
        int J = searchsorted_inner(yaxis, q, n);
        float y0 = yaxis[J];
        float y1 = yaxis[J + 1];
        int j2 = (J + 2 < n) ? J + 2 : n - 1;
        float y2 = yaxis[j2];
        float dy = y1 - y0;
        float t  = (q - y0) / dy;
        float t2 = t * t, t3 = t2 * t;
        float h0 = 1.0f - 3.0f * t2 + 2.0f * t3;
        float h1 = t - 2.0f * t2 + t3;
        float h2 = 3.0f * t2 - 2.0f * t3;
        float h3 = t3 - t2;
        float r  = dy / (y2 - y1);
        float4 w;
        w.x = h0;        // weight on out[.., J]
        w.y = h2;        // weight on out[.., J+1]
        w.z = h1;        // weight on (S[J+1,k]-S[J,k])
        w.w = h3 * r;    // weight on (S[J+2,k]-S[J+1,k])
        g_yw[k] = w;
        g_yJ[k] = J;
    }
}

// ─────────────── Specialized N=1024, 4-batches-per-CTA, batch-interleaved ───
// 512 threads/CTA, 2 k-slots per thread (k = t, t+512). One CTA handles output
// row `my` for 4 consecutive batches. Smem is batch-interleaved:
// rowC4[i] = (C_b0[i], .., C_b3[i]) so one LDS.128 at tap i serves 4 batches.
// g_xw loads hoisted above the barrier to overlap their latency with staging.
__global__ __launch_bounds__(512) void hermite2d_n1024_b4(
    const float* __restrict__ signal,
    float* __restrict__ out) {
    __shared__ float4 rowC4[1024];         // 16 KB, batch-interleaved

    const int t  = threadIdx.x;            // 0..511
    const int bm = blockIdx.x;
    const int bq = bm >> 10;               // batch quad
    const int my = bm & 1023;

    const int    J  = g_yJ[my];
    const float4 yw = g_yw[my];

    // weight loads are independent of smem — issue before staging/barrier
    const float4 w0 = g_xw[t];
    const float4 w1 = g_xw[t + 512];

    const float* __restrict__ base0 = signal + (((size_t)(4 * bq + 0) << 10) + (size_t)J) * 1024u;
    const float* __restrict__ base1 = base0 + (1u << 20);
    const float* __restrict__ base2 = base0 + (2u << 20);
    const float* __restrict__ base3 = base0 + (3u << 20);

    float D[4][2];                         // [bb][j] coalesced y-slope term

    #pragma unroll
    for (int j = 0; j < 2; j++) {
        const int k = t + 512 * j;
        float4 C;
        {
            float a = base0[k], c = base0[1024 + k], e = base0[2048 + k];
            C.x = yw.x * a + yw.y * c;
            D[0][j] = yw.z * (c - a) + yw.w * (e - c);
        }
        {
            float a = base1[k], c = base1[1024 + k], e = base1[2048 + k];
            C.y = yw.x * a + yw.y * c;
            D[1][j] = yw.z * (c - a) + yw.w * (e - c);
        }
        {
            float a = base2[k], c = base2[1024 + k], e = base2[2048 + k];
            C.z = yw.x * a + yw.y * c;
            D[2][j] = yw.z * (c - a) + yw.w * (e - c);
        }
        {
            float a = base3[k], c = base3[1024 + k], e = base3[2048 + k];
            C.w = yw.x * a + yw.y * c;
            D[3][j] = yw.z * (c - a) + yw.w * (e - c);
        }
        rowC4[k] = C;                      // STS.128, conflict-free
    }
    __syncthreads();

    float* __restrict__ o0 = out + (((size_t)(4 * bq + 0) << 10) + (size_t)my) * 1024u;
    float* __restrict__ o1 = o0 + (1u << 20);
    float* __restrict__ o2 = o0 + (2u << 20);
    float* __restrict__ o3 = o0 + (3u << 20);

    {
        const int k = t;
        const int I = __float_as_int(w0.w);
        const float4 p0 = rowC4[I];
        const float4 p1 = rowC4[I + 1];
        const float4 p2 = rowC4[I + 2];
        o0[k] = w0.x * p0.x + w0.y * p1.x + w0.z * p2.x + D[0][0];
        o1[k] = w0.x * p0.y + w0.y * p1.y + w0.z * p2.y + D[1][0];
        o2[k] = w0.x * p0.z + w0.y * p1.z + w0.z * p2.z + D[2][0];
        o3[k] = w0.x * p0.w + w0.y * p1.w + w0.z * p2.w + D[3][0];
    }
    {
        const int k = t + 512;
        const int I = __float_as_int(w1.w);
        const float4 p0 = rowC4[I];
        const float4 p1 = rowC4[I + 1];
        const float4 p2 = rowC4[I + 2];
        o0[k] = w1.x * p0.x + w1.y * p1.x + w1.z * p2.x + D[0][1];
        o1[k] = w1.x * p0.y + w1.y * p1.y + w1.z * p2.y + D[1][1];
        o2[k] = w1.x * p0.z + w1.y * p1.z + w1.z * p2.z + D[2][1];
        o3[k] = w1.x * p0.w + w1.y * p1.w + w1.z * p2.w + D[3][1];
    }
}

// ─────────────── Specialized N=1024, 1 row per CTA (B % 4 != 0) ─────────────
__global__ __launch_bounds__(256) void hermite2d_n1024(
    const float* __restrict__ signal,
    float* __restrict__ out) {
    __shared__ float rowC[1024];

    const int t  = threadIdx.x;
    const int bm = blockIdx.x;
    const int b  = bm >> 10;
    const int my = bm & 1023;

    const int    J  = g_yJ[my];
    const float4 yw = g_yw[my];

    const float* __restrict__ base = signal + (((size_t)b << 10) + (size_t)J) * 1024u;

    float D[4];
    #pragma unroll
    for (int j = 0; j < 4; j++) {
        const int k = t + 256 * j;
        float a = base[k];
        float c = base[1024 + k];
        float e = base[2048 + k];
        rowC[k] = yw.x * a + yw.y * c;
        D[j]    = yw.z * (c - a) + yw.w * (e - c);
    }
    __syncthreads();

    float* __restrict__ orow = out + (((size_t)b << 10) + (size_t)my) * 1024u;
    #pragma unroll
    for (int j = 0; j < 4; j++) {
        const int k = t + 256 * j;
        const float4 w = g_xw[k];
        const int I = __float_as_int(w.w);
        orow[k] = w.x * rowC[I] + w.y * rowC[I + 1] + w.z * rowC[I + 2] + D[j];
    }
}

// ───────────────────────── Generic fallback (any n % 4 == 0) ─────────────────
__global__ __launch_bounds__(256) void hermite2d_generic(
    const float* __restrict__ signal,
    float* __restrict__ out,
    int n) {
    extern __shared__ float sm[];          // 2*n floats
    float* rowC = sm;
    float* rowD = sm + n;

    int bm = blockIdx.x;
    int b  = bm / n;
    int my = bm - b * n;

    int    J  = g_yJ[my];
    float4 yw = g_yw[my];

    const float* base = signal + ((size_t)b * n + J) * (size_t)n;
    int nv = n >> 2;
    const float4* srcJ  = reinterpret_cast<const float4*>(base);
    const float4* srcJ1 = reinterpret_cast<const float4*>(base + n);
    const float4* srcJ2 = reinterpret_cast<const float4*>(base + 2 * (size_t)n);
    float4* dstC = reinterpret_cast<float4*>(rowC);
    float4* dstD = reinterpret_cast<float4*>(rowD);
    for (int i = threadIdx.x; i < nv; i += blockDim.x) {
        float4 a = srcJ[i];
        float4 c = srcJ1[i];
        float4 e = srcJ2[i];
        float4 C, Dv;
        C.x = yw.x * a.x + yw.y * c.x;
        C.y = yw.x * a.y + yw.y * c.y;
        C.z = yw.x * a.z + yw.y * c.z;
        C.w = yw.x * a.w + yw.y * c.w;
        Dv.x = yw.z * (c.x - a.x) + yw.w * (e.x - c.x);
        Dv.y = yw.z * (c.y - a.y) + yw.w * (e.y - c.y);
        Dv.z = yw.z * (c.z - a.z) + yw.w * (e.z - c.z);
        Dv.w = yw.z * (c.w - a.w) + yw.w * (e.w - c.w);
        dstC[i] = C;
        dstD[i] = Dv;
    }
    __syncthreads();

    float* orow = out + ((size_t)b * n + my) * (size_t)n;
    for (int k = threadIdx.x; k < n; k += blockDim.x) {
        float4 xw = g_xw[k];
        int I = __float_as_int(xw.w);
        orow[k] = xw.x * rowC[I] + xw.y * rowC[I + 1] + xw.z * rowC[I + 2] + rowD[k];
    }
}

extern "C" void kernel_launch(void* const* d_in, const int* in_sizes, int n_in,
                              void* d_out, int out_size) {
    const float* xaxis  = (const float*)d_in[0];
    const float* yaxis  = (const float*)d_in[1];
    const float* signal = (const float*)d_in[2];
    const float* xs     = (const float*)d_in[3];
    const float* ys     = (const float*)d_in[4];
    float* out = (float*)d_out;

    int n = in_sizes[0];                 // N (square grid, Mx = My = N)
    int B = in_sizes[2] / (n * n);       // batch

    precompute_weights<<<(n + 255) / 256, 256>>>(xaxis, yaxis, xs, ys, n);

    if (n == 1024 && (B % 4) == 0) {
        hermite2d_n1024_b4<<<(B / 4) * n, 512>>>(signal, out);
    } else if (n == 1024) {
        hermite2d_n1024<<<B * n, 256>>>(signal, out);
    } else {
        size_t smem = 2 * (size_t)n * sizeof(float);
        hermite2d_generic<<<B * n, 256, smem>>>(signal, out, n);
    }
}